// round 3
// baseline (speedup 1.0000x reference)
#include <cuda_runtime.h>
#include <cstdint>

#define NN 100000
#define NE 1600000
#define IND 256
#define HID 128
#define OUTD 64

// scratch (allocation-free: __device__ globals)
__device__ int   g_is64;
__device__ int   g_eidx[2 * NE];           // normalized int32 edge index
__device__ float g_deg[NN];
__device__ float g_dis[NN];
__device__ float g_h1[(size_t)NN * HID];   // x @ W1
__device__ float g_a1[(size_t)NN * HID];   // aggregated, then relu'ed hidden
__device__ float g_h2[(size_t)NN * OUTD];  // a1 @ W2

// ---------------------------------------------------------------------------
// edge-index dtype detection + normalization to int32
// ---------------------------------------------------------------------------
__global__ void k_detect(const int* __restrict__ ei32) {
    if (threadIdx.x == 0 && blockIdx.x == 0) {
        int is64 = 1;
        for (int i = 0; i < 512; i++) {
            if (ei32[2 * i + 1] != 0) { is64 = 0; break; }
        }
        g_is64 = is64;
    }
}

__global__ void k_convert(const void* __restrict__ ei, int m /* = 2*E */) {
    const int is64 = g_is64;
    const long long* p64 = (const long long*)ei;
    const int* p32 = (const int*)ei;
    for (int i = blockIdx.x * blockDim.x + threadIdx.x; i < m;
         i += gridDim.x * blockDim.x) {
        int v = is64 ? (int)p64[i] : p32[i];
        v = min(max(v, 0), NN - 1);  // safety clamp
        g_eidx[i] = v;
    }
}

// ---------------------------------------------------------------------------
// degree / normalization
// ---------------------------------------------------------------------------
__global__ void k_deg_init(int n) {
    int i = blockIdx.x * blockDim.x + threadIdx.x;
    if (i < n) g_deg[i] = 1.0f;  // self-loop
}

__global__ void k_deg_count(int e) {
    for (int i = blockIdx.x * blockDim.x + threadIdx.x; i < e;
         i += gridDim.x * blockDim.x) {
        atomicAdd(&g_deg[g_eidx[e + i]], 1.0f);  // col = target
    }
}

__global__ void k_dis(int n) {
    int i = blockIdx.x * blockDim.x + threadIdx.x;
    if (i < n) g_dis[i] = rsqrtf(g_deg[i]);
}

// ---------------------------------------------------------------------------
// tiled SGEMM: C[M,N] = A[M,K] @ B[K,N], BN == N (full-width W tile)
// ---------------------------------------------------------------------------
template <int K, int N, int BM, int BK, int TM, int TN>
__global__ __launch_bounds__((BM / TM) * (N / TN)) void sgemm_kernel(
    const float* __restrict__ A, const float* __restrict__ B,
    float* __restrict__ C, int M) {
    constexpr int BN = N;
    constexpr int THREADS = (BM / TM) * (BN / TN);
    __shared__ float As[BK][BM];
    __shared__ float Bs[BK][BN];

    const int tid = threadIdx.x;
    const int tx = tid % (BN / TN);
    const int ty = tid / (BN / TN);
    const int m0 = blockIdx.x * BM;

    float acc[TM][TN] = {};

    for (int k0 = 0; k0 < K; k0 += BK) {
        // A tile, stored transposed into smem
        constexpr int A_LOADS = (BM * BK / 4) / THREADS;
#pragma unroll
        for (int l = 0; l < A_LOADS; l++) {
            int idx = tid + l * THREADS;       // float4 index in tile
            int r = idx / (BK / 4);            // row in tile
            int kc = (idx % (BK / 4)) * 4;     // k offset in tile
            int row = m0 + r;
            if (row >= M) row = M - 1;         // clamp (stores are guarded)
            float4 v = *(const float4*)(A + (size_t)row * K + k0 + kc);
            As[kc + 0][r] = v.x;
            As[kc + 1][r] = v.y;
            As[kc + 2][r] = v.z;
            As[kc + 3][r] = v.w;
        }
        // B tile: rows k0..k0+BK, full width -> contiguous
        constexpr int B_LOADS = (BK * BN / 4) / THREADS;
#pragma unroll
        for (int l = 0; l < B_LOADS; l++) {
            int idx = tid + l * THREADS;
            *(float4*)(&Bs[0][0] + idx * 4) =
                *(const float4*)(B + (size_t)k0 * N + idx * 4);
        }
        __syncthreads();

#pragma unroll
        for (int k = 0; k < BK; k++) {
            float a[TM], b[TN];
#pragma unroll
            for (int i = 0; i < TM; i++) a[i] = As[k][ty * TM + i];
#pragma unroll
            for (int j = 0; j < TN; j++) b[j] = Bs[k][tx * TN + j];
#pragma unroll
            for (int i = 0; i < TM; i++)
#pragma unroll
                for (int j = 0; j < TN; j++)
                    acc[i][j] = fmaf(a[i], b[j], acc[i][j]);
        }
        __syncthreads();
    }

#pragma unroll
    for (int i = 0; i < TM; i++) {
        int row = m0 + ty * TM + i;
        if (row < M) {
#pragma unroll
            for (int j = 0; j < TN; j += 4) {
                float4 v = make_float4(acc[i][j], acc[i][j + 1],
                                       acc[i][j + 2], acc[i][j + 3]);
                *(float4*)(C + (size_t)row * N + tx * TN + j) = v;
            }
        }
    }
}

// ---------------------------------------------------------------------------
// aggregation: init with self-loop contribution, then edge scatter (red.v4)
// ---------------------------------------------------------------------------
__device__ __forceinline__ void red_add_v4(float* dst, float4 v) {
    asm volatile("red.global.add.v4.f32 [%0], {%1,%2,%3,%4};" ::"l"(dst),
                 "f"(v.x), "f"(v.y), "f"(v.z), "f"(v.w)
                 : "memory");
}

__global__ void k_agg_init128(int n) {
    int idx = blockIdx.x * blockDim.x + threadIdx.x;  // float4 index
    int total = n * (HID / 4);
    if (idx >= total) return;
    int node = idx / (HID / 4);
    float d = g_dis[node];
    float s = d * d;
    float4 v = ((const float4*)g_h1)[idx];
    v.x *= s; v.y *= s; v.z *= s; v.w *= s;
    ((float4*)g_a1)[idx] = v;
}

// one warp per edge; 32 lanes x float4 = 128 floats
__global__ __launch_bounds__(256) void k_edge128(int e) {
    int warp = (blockIdx.x * blockDim.x + threadIdx.x) >> 5;
    int lane = threadIdx.x & 31;
    if (warp >= e) return;
    int r = g_eidx[warp];
    int c = g_eidx[e + warp];
    float nrm = g_dis[r] * g_dis[c];
    float4 v = ((const float4*)(g_h1 + (size_t)r * HID))[lane];
    v.x *= nrm; v.y *= nrm; v.z *= nrm; v.w *= nrm;
    red_add_v4(g_a1 + (size_t)c * HID + lane * 4, v);
}

__global__ void k_relu_bias(const float* __restrict__ b1, int n) {
    int idx = blockIdx.x * blockDim.x + threadIdx.x;  // float4 index
    int total = n * (HID / 4);
    if (idx >= total) return;
    int d4 = idx % (HID / 4);
    float4 b = ((const float4*)b1)[d4];
    float4 v = ((float4*)g_a1)[idx];
    v.x = fmaxf(v.x + b.x, 0.0f);
    v.y = fmaxf(v.y + b.y, 0.0f);
    v.z = fmaxf(v.z + b.z, 0.0f);
    v.w = fmaxf(v.w + b.w, 0.0f);
    ((float4*)g_a1)[idx] = v;
}

__global__ void k_out_init64(const float* __restrict__ b2,
                             float* __restrict__ out, int n) {
    int idx = blockIdx.x * blockDim.x + threadIdx.x;  // float4 index
    int total = n * (OUTD / 4);
    if (idx >= total) return;
    int node = idx / (OUTD / 4);
    int d4 = idx % (OUTD / 4);
    float d = g_dis[node];
    float s = d * d;
    float4 b = ((const float4*)b2)[d4];
    float4 v = ((const float4*)g_h2)[idx];
    v.x = v.x * s + b.x;
    v.y = v.y * s + b.y;
    v.z = v.z * s + b.z;
    v.w = v.w * s + b.w;
    ((float4*)out)[idx] = v;
}

// half-warp (16 lanes x float4 = 64 floats) per edge; each warp does 2 edges
__global__ __launch_bounds__(256) void k_edge64(float* __restrict__ out,
                                                int e) {
    int warp = (blockIdx.x * blockDim.x + threadIdx.x) >> 5;
    int lane = threadIdx.x & 31;
    int edge = warp * 2 + (lane >> 4);
    int l16 = lane & 15;
    if (edge >= e) return;
    int r = g_eidx[edge];
    int c = g_eidx[e + edge];
    float nrm = g_dis[r] * g_dis[c];
    float4 v = ((const float4*)(g_h2 + (size_t)r * OUTD))[l16];
    v.x *= nrm; v.y *= nrm; v.z *= nrm; v.w *= nrm;
    red_add_v4(out + (size_t)c * OUTD + l16 * 4, v);
}

// ---------------------------------------------------------------------------
// launch
// ---------------------------------------------------------------------------
extern "C" void kernel_launch(void* const* d_in, const int* in_sizes, int n_in,
                              void* d_out, int out_size) {
    // bind inputs by element count (robust against metadata ordering)
    const float* x = nullptr;
    const void* ei = nullptr;
    const float* W1 = nullptr;
    const float* b1 = nullptr;
    const float* W2 = nullptr;
    const float* b2 = nullptr;
    for (int i = 0; i < n_in; i++) {
        switch (in_sizes[i]) {
            case NN * IND:   x  = (const float*)d_in[i]; break;
            case 2 * NE:     ei = d_in[i];               break;
            case IND * HID:  W1 = (const float*)d_in[i]; break;
            case HID:        b1 = (const float*)d_in[i]; break;
            case HID * OUTD: W2 = (const float*)d_in[i]; break;
            case OUTD:       b2 = (const float*)d_in[i]; break;
            default: break;
        }
    }
    float* out = (float*)d_out;
    const int n = NN;
    const int e = NE;

    float* h1;  cudaGetSymbolAddress((void**)&h1, g_h1);
    float* a1;  cudaGetSymbolAddress((void**)&a1, g_a1);
    float* h2;  cudaGetSymbolAddress((void**)&h2, g_h2);

    // normalize edge index to int32 (handles int32-or-int64 input)
    k_detect<<<1, 32>>>((const int*)ei);
    k_convert<<<2048, 256>>>(ei, 2 * e);

    // degree / norm
    k_deg_init<<<(n + 255) / 256, 256>>>(n);
    k_deg_count<<<1024, 256>>>(e);
    k_dis<<<(n + 255) / 256, 256>>>(n);

    // layer 1: h1 = x @ W1
    sgemm_kernel<IND, HID, 64, 32, 8, 8>
        <<<(n + 63) / 64, 128>>>(x, W1, h1, n);
    {
        int tot = n * (HID / 4);
        k_agg_init128<<<(tot + 255) / 256, 256>>>(n);
    }
    {
        long long thr = (long long)e * 32;
        k_edge128<<<(int)((thr + 255) / 256), 256>>>(e);
    }
    {
        int tot = n * (HID / 4);
        k_relu_bias<<<(tot + 255) / 256, 256>>>(b1, n);
    }

    // layer 2: h2 = a1 @ W2
    sgemm_kernel<HID, OUTD, 64, 32, 8, 4>
        <<<(n + 63) / 64, 128>>>(a1, W2, h2, n);
    {
        int tot = n * (OUTD / 4);
        k_out_init64<<<(tot + 255) / 256, 256>>>(b2, out, n);
    }
    {
        long long warps = ((long long)e + 1) / 2;
        long long thr = warps * 32;
        k_edge64<<<(int)((thr + 255) / 256), 256>>>(out, e);
    }
}

// round 6
// speedup vs baseline: 1.0639x; 1.0639x over previous
#include <cuda_runtime.h>
#include <cstdint>

#define NN 100000
#define NE 1600000
#define IND 256
#define HID 128
#define OUTD 64

// scratch (allocation-free: __device__ globals)
__device__ int   g_is64;
__device__ int   g_eidx[2 * NE];           // normalized int32 edge index
__device__ float g_deg[NN];
__device__ float g_dis[NN];
__device__ float g_h1[(size_t)NN * HID];   // (x @ W1) * dis[row]
__device__ float g_a1[(size_t)NN * HID];   // aggregation buffer / relu'ed hidden

// ---------------------------------------------------------------------------
// edge-index dtype detection + normalization to int32
// ---------------------------------------------------------------------------
__global__ void k_detect(const int* __restrict__ ei32) {
    if (threadIdx.x == 0 && blockIdx.x == 0) {
        int is64 = 1;
        for (int i = 0; i < 512; i++) {
            if (ei32[2 * i + 1] != 0) { is64 = 0; break; }
        }
        g_is64 = is64;
    }
}

__global__ void k_convert(const void* __restrict__ ei, int m /* = 2*E */) {
    const int is64 = g_is64;
    const long long* p64 = (const long long*)ei;
    const int* p32 = (const int*)ei;
    for (int i = blockIdx.x * blockDim.x + threadIdx.x; i < m;
         i += gridDim.x * blockDim.x) {
        int v = is64 ? (int)p64[i] : p32[i];
        v = min(max(v, 0), NN - 1);  // safety clamp
        g_eidx[i] = v;
    }
}

// ---------------------------------------------------------------------------
// degree / normalization
// ---------------------------------------------------------------------------
__global__ void k_deg_init(int n) {
    int i = blockIdx.x * blockDim.x + threadIdx.x;
    if (i < n) g_deg[i] = 1.0f;  // self-loop
}

__global__ void k_deg_count(int e) {
    for (int i = blockIdx.x * blockDim.x + threadIdx.x; i < e;
         i += gridDim.x * blockDim.x) {
        atomicAdd(&g_deg[g_eidx[e + i]], 1.0f);  // col = target
    }
}

__global__ void k_dis(int n) {
    int i = blockIdx.x * blockDim.x + threadIdx.x;
    if (i < n) g_dis[i] = rsqrtf(g_deg[i]);
}

// ---------------------------------------------------------------------------
// 3xTF32 tensor-core GEMM: C[M,N] = (A[M,K] @ B[K,N]) * scale[row]
// BN == N (full-width weight tile). mma.sync.m16n8k8 tf32, hi/lo split in regs.
// ---------------------------------------------------------------------------
__device__ __forceinline__ void f32_split(float v, uint32_t& hi, uint32_t& lo) {
    asm("cvt.rna.tf32.f32 %0, %1;" : "=r"(hi) : "f"(v));
    float rem = v - __uint_as_float(hi);
    asm("cvt.rna.tf32.f32 %0, %1;" : "=r"(lo) : "f"(rem));
}

__device__ __forceinline__ void mma_tf32(float* c, const uint32_t* a,
                                         const uint32_t* b) {
    asm volatile(
        "mma.sync.aligned.m16n8k8.row.col.f32.tf32.tf32.f32 "
        "{%0,%1,%2,%3}, {%4,%5,%6,%7}, {%8,%9}, {%0,%1,%2,%3};"
        : "+f"(c[0]), "+f"(c[1]), "+f"(c[2]), "+f"(c[3])
        : "r"(a[0]), "r"(a[1]), "r"(a[2]), "r"(a[3]), "r"(b[0]), "r"(b[1]));
}

template <int K, int N, int BM, int BK, int WM, int WN>
__global__ __launch_bounds__((BM / WM) * (N / WN) * 32) void tf32_gemm(
    const float* __restrict__ A, const float* __restrict__ B,
    float* __restrict__ C, const float* __restrict__ scale, int M) {
    constexpr int BN = N;
    constexpr int WARPS_N = BN / WN;
    constexpr int NWARPS = (BM / WM) * WARPS_N;
    constexpr int THREADS = NWARPS * 32;
    constexpr int MT = WM / 16;
    constexpr int NT = WN / 8;
    constexpr int A_LOADS = (BM * BK / 4) / THREADS;
    constexpr int B_LOADS = (BK * BN / 4) / THREADS;
    constexpr int PAD = 8;

    __shared__ float As[BK][BM + PAD];
    __shared__ float Bs[BK][BN + PAD];

    const int tid = threadIdx.x;
    const int wid = tid >> 5;
    const int lane = tid & 31;
    const int p = lane >> 2;   // 0..7
    const int q = lane & 3;    // 0..3
    const int wm0 = (wid / WARPS_N) * WM;
    const int wn0 = (wid % WARPS_N) * WN;
    const int m0 = blockIdx.x * BM;

    float acc[MT][NT][4] = {};

    float4 aReg[A_LOADS], bReg[B_LOADS];
    // prefetch k0 = 0
#pragma unroll
    for (int l = 0; l < A_LOADS; l++) {
        int idx = tid + l * THREADS;
        int r = idx / (BK / 4);
        int kc = (idx % (BK / 4)) * 4;
        int row = m0 + r;
        if (row >= M) row = M - 1;
        aReg[l] = *(const float4*)(A + (size_t)row * K + kc);
    }
#pragma unroll
    for (int l = 0; l < B_LOADS; l++) {
        int flat = (tid + l * THREADS) * 4;
        bReg[l] = *(const float4*)(B + flat);
    }

    for (int k0 = 0; k0 < K; k0 += BK) {
        // commit staged tiles to smem
#pragma unroll
        for (int l = 0; l < A_LOADS; l++) {
            int idx = tid + l * THREADS;
            int r = idx / (BK / 4);
            int kc = (idx % (BK / 4)) * 4;
            As[kc + 0][r] = aReg[l].x;
            As[kc + 1][r] = aReg[l].y;
            As[kc + 2][r] = aReg[l].z;
            As[kc + 3][r] = aReg[l].w;
        }
#pragma unroll
        for (int l = 0; l < B_LOADS; l++) {
            int flat = (tid + l * THREADS) * 4;
            int k = flat / BN;
            int n = flat % BN;
            *(float4*)(&Bs[k][n]) = bReg[l];
        }
        __syncthreads();

        // prefetch next tiles
        if (k0 + BK < K) {
#pragma unroll
            for (int l = 0; l < A_LOADS; l++) {
                int idx = tid + l * THREADS;
                int r = idx / (BK / 4);
                int kc = (idx % (BK / 4)) * 4;
                int row = m0 + r;
                if (row >= M) row = M - 1;
                aReg[l] = *(const float4*)(A + (size_t)row * K + k0 + BK + kc);
            }
#pragma unroll
            for (int l = 0; l < B_LOADS; l++) {
                int flat = (tid + l * THREADS) * 4;
                bReg[l] = *(const float4*)(B + (size_t)(k0 + BK) * N + flat);
            }
        }

#pragma unroll
        for (int kk = 0; kk < BK; kk += 8) {
            uint32_t ahi[MT][4], alo[MT][4];
#pragma unroll
            for (int mt = 0; mt < MT; mt++) {
                int r0 = wm0 + mt * 16 + p;
                f32_split(As[kk + q][r0],         ahi[mt][0], alo[mt][0]);
                f32_split(As[kk + q][r0 + 8],     ahi[mt][1], alo[mt][1]);
                f32_split(As[kk + q + 4][r0],     ahi[mt][2], alo[mt][2]);
                f32_split(As[kk + q + 4][r0 + 8], ahi[mt][3], alo[mt][3]);
            }
            uint32_t bhi[NT][2], blo[NT][2];
#pragma unroll
            for (int nt = 0; nt < NT; nt++) {
                int c0 = wn0 + nt * 8 + p;
                f32_split(Bs[kk + q][c0],     bhi[nt][0], blo[nt][0]);
                f32_split(Bs[kk + q + 4][c0], bhi[nt][1], blo[nt][1]);
            }
#pragma unroll
            for (int mt = 0; mt < MT; mt++)
#pragma unroll
                for (int nt = 0; nt < NT; nt++) {
                    mma_tf32(acc[mt][nt], ahi[mt], bhi[nt]);
                    mma_tf32(acc[mt][nt], ahi[mt], blo[nt]);
                    mma_tf32(acc[mt][nt], alo[mt], bhi[nt]);
                }
        }
        __syncthreads();
    }

    // epilogue: scale rows by scale[row], store
#pragma unroll
    for (int mt = 0; mt < MT; mt++) {
        int row0 = m0 + wm0 + mt * 16 + p;
        int row1 = row0 + 8;
        float s0 = (row0 < M) ? scale[row0] : 0.0f;
        float s1 = (row1 < M) ? scale[row1] : 0.0f;
#pragma unroll
        for (int nt = 0; nt < NT; nt++) {
            int col = wn0 + nt * 8 + 2 * q;
            if (row0 < M) {
                float2 v = make_float2(acc[mt][nt][0] * s0, acc[mt][nt][1] * s0);
                *(float2*)(C + (size_t)row0 * N + col) = v;
            }
            if (row1 < M) {
                float2 v = make_float2(acc[mt][nt][2] * s1, acc[mt][nt][3] * s1);
                *(float2*)(C + (size_t)row1 * N + col) = v;
            }
        }
    }
}

// ---------------------------------------------------------------------------
// aggregation: init = self contribution (plain copy), edge scatter via red.v4
// ---------------------------------------------------------------------------
__device__ __forceinline__ void red_add_v4(float* dst, float4 v) {
    asm volatile("red.global.add.v4.f32 [%0], {%1,%2,%3,%4};" ::"l"(dst),
                 "f"(v.x), "f"(v.y), "f"(v.z), "f"(v.w)
                 : "memory");
}

__global__ void k_copy(const float* __restrict__ src, float* __restrict__ dst,
                       int total4) {
    int idx = blockIdx.x * blockDim.x + threadIdx.x;
    if (idx < total4) ((float4*)dst)[idx] = ((const float4*)src)[idx];
}

// one warp per edge; 32 lanes x float4 = 128 floats (pure gather + red)
__global__ __launch_bounds__(256) void k_edge128(int e) {
    int warp = (blockIdx.x * blockDim.x + threadIdx.x) >> 5;
    int lane = threadIdx.x & 31;
    if (warp >= e) return;
    int r = g_eidx[warp];
    int c = g_eidx[e + warp];
    float4 v = ((const float4*)(g_h1 + (size_t)r * HID))[lane];
    red_add_v4(g_a1 + (size_t)c * HID + lane * 4, v);
}

// a1 = relu(dis[node] * a1 + b1)
__global__ void k_relu_bias(const float* __restrict__ b1, int n) {
    int idx = blockIdx.x * blockDim.x + threadIdx.x;  // float4 index
    int total = n * (HID / 4);
    if (idx >= total) return;
    int node = idx / (HID / 4);
    int d4 = idx % (HID / 4);
    float s = g_dis[node];
    float4 b = ((const float4*)b1)[d4];
    float4 v = ((float4*)g_a1)[idx];
    v.x = fmaxf(fmaf(v.x, s, b.x), 0.0f);
    v.y = fmaxf(fmaf(v.y, s, b.y), 0.0f);
    v.z = fmaxf(fmaf(v.z, s, b.z), 0.0f);
    v.w = fmaxf(fmaf(v.w, s, b.w), 0.0f);
    ((float4*)g_a1)[idx] = v;
}

// half-warp (16 lanes x float4 = 64 floats) per edge; each warp does 2 edges
__global__ __launch_bounds__(256) void k_edge64(float* __restrict__ out,
                                                int e) {
    int warp = (blockIdx.x * blockDim.x + threadIdx.x) >> 5;
    int lane = threadIdx.x & 31;
    int edge = warp * 2 + (lane >> 4);
    int l16 = lane & 15;
    if (edge >= e) return;
    int r = g_eidx[edge];
    int c = g_eidx[e + edge];
    float4 v = ((const float4*)(out + 0) + 0)[0];  // placeholder avoided below
    (void)v;
    float4 w = ((const float4*)(/*h2s=*/nullptr))[0];
    (void)w;
    // (real body below)
}

// real edge64: gathers from h2s buffer (= out) would race; use separate src
__device__ float g_h2[(size_t)NN * OUTD];  // (a1 @ W2) * dis[row]

__global__ __launch_bounds__(256) void k_edge64b(float* __restrict__ out,
                                                 int e) {
    int warp = (blockIdx.x * blockDim.x + threadIdx.x) >> 5;
    int lane = threadIdx.x & 31;
    int edge = warp * 2 + (lane >> 4);
    int l16 = lane & 15;
    if (edge >= e) return;
    int r = g_eidx[edge];
    int c = g_eidx[e + edge];
    float4 v = ((const float4*)(g_h2 + (size_t)r * OUTD))[l16];
    red_add_v4(out + (size_t)c * OUTD + l16 * 4, v);
}

// out = dis[node] * out + b2
__global__ void k_out_fix(const float* __restrict__ b2, float* __restrict__ out,
                          int n) {
    int idx = blockIdx.x * blockDim.x + threadIdx.x;  // float4 index
    int total = n * (OUTD / 4);
    if (idx >= total) return;
    int node = idx / (OUTD / 4);
    int d4 = idx % (OUTD / 4);
    float s = g_dis[node];
    float4 b = ((const float4*)b2)[d4];
    float4 v = ((float4*)out)[idx];
    v.x = fmaf(v.x, s, b.x);
    v.y = fmaf(v.y, s, b.y);
    v.z = fmaf(v.z, s, b.z);
    v.w = fmaf(v.w, s, b.w);
    ((float4*)out)[idx] = v;
}

// ---------------------------------------------------------------------------
// launch
// ---------------------------------------------------------------------------
extern "C" void kernel_launch(void* const* d_in, const int* in_sizes, int n_in,
                              void* d_out, int out_size) {
    // bind inputs by element count (robust against metadata ordering)
    const float* x = nullptr;
    const void* ei = nullptr;
    const float* W1 = nullptr;
    const float* b1 = nullptr;
    const float* W2 = nullptr;
    const float* b2 = nullptr;
    for (int i = 0; i < n_in; i++) {
        switch (in_sizes[i]) {
            case NN * IND:   x  = (const float*)d_in[i]; break;
            case 2 * NE:     ei = d_in[i];               break;
            case IND * HID:  W1 = (const float*)d_in[i]; break;
            case HID:        b1 = (const float*)d_in[i]; break;
            case HID * OUTD: W2 = (const float*)d_in[i]; break;
            case OUTD:       b2 = (const float*)d_in[i]; break;
            default: break;
        }
    }
    float* out = (float*)d_out;
    const int n = NN;
    const int e = NE;

    float* h1;  cudaGetSymbolAddress((void**)&h1, g_h1);
    float* a1;  cudaGetSymbolAddress((void**)&a1, g_a1);
    float* h2;  cudaGetSymbolAddress((void**)&h2, g_h2);
    float* dis; cudaGetSymbolAddress((void**)&dis, g_dis);

    // normalize edge index to int32 (handles int32-or-int64 input)
    k_detect<<<1, 32>>>((const int*)ei);
    k_convert<<<2048, 256>>>(ei, 2 * e);

    // degree / norm
    k_deg_init<<<(n + 255) / 256, 256>>>(n);
    k_deg_count<<<1024, 256>>>(e);
    k_dis<<<(n + 255) / 256, 256>>>(n);

    // layer 1: h1 = (x @ W1) * dis[row]   (3xTF32 tensor GEMM)
    tf32_gemm<IND, HID, 128, 32, 64, 32>
        <<<(n + 127) / 128, 256>>>(x, W1, h1, dis, n);
    {
        int tot4 = n * (HID / 4);
        k_copy<<<(tot4 + 255) / 256, 256>>>(h1, a1, tot4);  // self contribution
    }
    {
        long long thr = (long long)e * 32;
        k_edge128<<<(int)((thr + 255) / 256), 256>>>(e);
    }
    {
        int tot = n * (HID / 4);
        k_relu_bias<<<(tot + 255) / 256, 256>>>(b1, n);
    }

    // layer 2: out = (a1 @ W2) * dis[row] goes to g_h2; out init = h2s copy
    tf32_gemm<HID, OUTD, 128, 32, 32, 32>
        <<<(n + 127) / 128, 256>>>(a1, W2, h2, dis, n);
    {
        int tot4 = n * (OUTD / 4);
        k_copy<<<(tot4 + 255) / 256, 256>>>(h2, out, tot4);  // self contribution
    }
    {
        long long warps = ((long long)e + 1) / 2;
        long long thr = warps * 32;
        k_edge64b<<<(int)((thr + 255) / 256), 256>>>(out, e);
    }
    {
        int tot = n * (OUTD / 4);
        k_out_fix<<<(tot + 255) / 256, 256>>>(b2, out, n);
    }
}

// round 7
// speedup vs baseline: 1.6180x; 1.5207x over previous
#include <cuda_runtime.h>
#include <cstdint>

#define NN 100000
#define NE 1600000
#define IND 256
#define HID 128
#define OUTD 64
#define NB ((NN + 1023) / 1024)   // scan blocks

// scratch (allocation-free: __device__ globals)
__device__ int   g_is64;
__device__ int   g_eidx[2 * NE];           // normalized int32 edge index
__device__ int   g_degi[NN];               // in-degree (excl self)
__device__ int   g_scan[NN];               // block-local inclusive scan
__device__ int   g_bsum[NB];               // per-block totals
__device__ int   g_boff[NB + 1];           // scanned block totals
__device__ int   g_off[NN + 1];            // CSR offsets (by destination)
__device__ int   g_cur[NN];                // scatter cursors
__device__ int   g_src[NE];                // CSR source ids
__device__ float g_dis[NN];
__device__ float g_h1[(size_t)NN * HID];   // (x @ W1) * dis[row]
__device__ float g_a1[(size_t)NN * HID];   // relu'ed hidden
__device__ float g_h2[(size_t)NN * OUTD];  // (a1 @ W2) * dis[row]

// ---------------------------------------------------------------------------
// edge-index dtype detection + normalization to int32
// ---------------------------------------------------------------------------
__global__ void k_detect(const int* __restrict__ ei32) {
    if (threadIdx.x == 0 && blockIdx.x == 0) {
        int is64 = 1;
        for (int i = 0; i < 512; i++) {
            if (ei32[2 * i + 1] != 0) { is64 = 0; break; }
        }
        g_is64 = is64;
    }
}

__global__ void k_convert(const void* __restrict__ ei, int m /* = 2*E */) {
    const int is64 = g_is64;
    const long long* p64 = (const long long*)ei;
    const int* p32 = (const int*)ei;
    for (int i = blockIdx.x * blockDim.x + threadIdx.x; i < m;
         i += gridDim.x * blockDim.x) {
        int v = is64 ? (int)p64[i] : p32[i];
        v = min(max(v, 0), NN - 1);  // safety clamp
        g_eidx[i] = v;
    }
}

// ---------------------------------------------------------------------------
// degree histogram + prefix scan -> CSR offsets
// ---------------------------------------------------------------------------
__global__ void k_deg_zero(int n) {
    int i = blockIdx.x * blockDim.x + threadIdx.x;
    if (i < n) g_degi[i] = 0;
}

__global__ void k_deg_count(int e) {
    for (int i = blockIdx.x * blockDim.x + threadIdx.x; i < e;
         i += gridDim.x * blockDim.x) {
        atomicAdd(&g_degi[g_eidx[e + i]], 1);  // col = target
    }
}

__global__ void k_dis(int n) {
    int i = blockIdx.x * blockDim.x + threadIdx.x;
    if (i < n) g_dis[i] = rsqrtf((float)(g_degi[i] + 1));  // +1 self-loop
}

__global__ __launch_bounds__(1024) void k_scan1(int n) {
    __shared__ int sh[1024];
    int i = blockIdx.x * 1024 + threadIdx.x;
    int v = (i < n) ? g_degi[i] : 0;
    sh[threadIdx.x] = v;
    __syncthreads();
#pragma unroll
    for (int d = 1; d < 1024; d <<= 1) {
        int t = (threadIdx.x >= d) ? sh[threadIdx.x - d] : 0;
        __syncthreads();
        sh[threadIdx.x] += t;
        __syncthreads();
    }
    if (i < n) g_scan[i] = sh[threadIdx.x];
    if (threadIdx.x == 1023) g_bsum[blockIdx.x] = sh[1023];
}

__global__ void k_scan2() {
    if (threadIdx.x == 0 && blockIdx.x == 0) {
        int acc = 0;
        g_boff[0] = 0;
        for (int b = 0; b < NB; b++) {
            acc += g_bsum[b];
            g_boff[b + 1] = acc;
        }
    }
}

__global__ void k_scan3(int n) {
    int i = blockIdx.x * blockDim.x + threadIdx.x;
    if (i >= n) return;
    int incl = g_scan[i] + g_boff[i >> 10];
    int start = incl - g_degi[i];
    g_off[i] = start;
    g_cur[i] = start;
    if (i == n - 1) g_off[n] = incl;
}

__global__ void k_scatter(int e) {
    for (int i = blockIdx.x * blockDim.x + threadIdx.x; i < e;
         i += gridDim.x * blockDim.x) {
        int c = g_eidx[e + i];
        int r = g_eidx[i];
        int pos = atomicAdd(&g_cur[c], 1);
        g_src[pos] = r;
    }
}

// ---------------------------------------------------------------------------
// 3xTF32 tensor-core GEMM: C[M,N] = (A[M,K] @ B[K,N]) * scale[row]
// ---------------------------------------------------------------------------
__device__ __forceinline__ void f32_split(float v, uint32_t& hi, uint32_t& lo) {
    asm("cvt.rna.tf32.f32 %0, %1;" : "=r"(hi) : "f"(v));
    float rem = v - __uint_as_float(hi);
    asm("cvt.rna.tf32.f32 %0, %1;" : "=r"(lo) : "f"(rem));
}

__device__ __forceinline__ void mma_tf32(float* c, const uint32_t* a,
                                         const uint32_t* b) {
    asm volatile(
        "mma.sync.aligned.m16n8k8.row.col.f32.tf32.tf32.f32 "
        "{%0,%1,%2,%3}, {%4,%5,%6,%7}, {%8,%9}, {%0,%1,%2,%3};"
        : "+f"(c[0]), "+f"(c[1]), "+f"(c[2]), "+f"(c[3])
        : "r"(a[0]), "r"(a[1]), "r"(a[2]), "r"(a[3]), "r"(b[0]), "r"(b[1]));
}

template <int K, int N, int BM, int BK, int WM, int WN>
__global__ __launch_bounds__((BM / WM) * (N / WN) * 32) void tf32_gemm(
    const float* __restrict__ A, const float* __restrict__ B,
    float* __restrict__ C, const float* __restrict__ scale, int M) {
    constexpr int BN = N;
    constexpr int WARPS_N = BN / WN;
    constexpr int NWARPS = (BM / WM) * WARPS_N;
    constexpr int THREADS = NWARPS * 32;
    constexpr int MT = WM / 16;
    constexpr int NT = WN / 8;
    constexpr int A_LOADS = (BM * BK / 4) / THREADS;
    constexpr int B_LOADS = (BK * BN / 4) / THREADS;
    constexpr int PAD = 8;

    __shared__ float As[BK][BM + PAD];
    __shared__ float Bs[BK][BN + PAD];

    const int tid = threadIdx.x;
    const int wid = tid >> 5;
    const int lane = tid & 31;
    const int p = lane >> 2;   // 0..7
    const int q = lane & 3;    // 0..3
    const int wm0 = (wid / WARPS_N) * WM;
    const int wn0 = (wid % WARPS_N) * WN;
    const int m0 = blockIdx.x * BM;

    float acc[MT][NT][4] = {};

    float4 aReg[A_LOADS], bReg[B_LOADS];
#pragma unroll
    for (int l = 0; l < A_LOADS; l++) {
        int idx = tid + l * THREADS;
        int r = idx / (BK / 4);
        int kc = (idx % (BK / 4)) * 4;
        int row = m0 + r;
        if (row >= M) row = M - 1;
        aReg[l] = *(const float4*)(A + (size_t)row * K + kc);
    }
#pragma unroll
    for (int l = 0; l < B_LOADS; l++) {
        int flat = (tid + l * THREADS) * 4;
        bReg[l] = *(const float4*)(B + flat);
    }

    for (int k0 = 0; k0 < K; k0 += BK) {
#pragma unroll
        for (int l = 0; l < A_LOADS; l++) {
            int idx = tid + l * THREADS;
            int r = idx / (BK / 4);
            int kc = (idx % (BK / 4)) * 4;
            As[kc + 0][r] = aReg[l].x;
            As[kc + 1][r] = aReg[l].y;
            As[kc + 2][r] = aReg[l].z;
            As[kc + 3][r] = aReg[l].w;
        }
#pragma unroll
        for (int l = 0; l < B_LOADS; l++) {
            int flat = (tid + l * THREADS) * 4;
            int k = flat / BN;
            int n = flat % BN;
            *(float4*)(&Bs[k][n]) = bReg[l];
        }
        __syncthreads();

        if (k0 + BK < K) {
#pragma unroll
            for (int l = 0; l < A_LOADS; l++) {
                int idx = tid + l * THREADS;
                int r = idx / (BK / 4);
                int kc = (idx % (BK / 4)) * 4;
                int row = m0 + r;
                if (row >= M) row = M - 1;
                aReg[l] = *(const float4*)(A + (size_t)row * K + k0 + BK + kc);
            }
#pragma unroll
            for (int l = 0; l < B_LOADS; l++) {
                int flat = (tid + l * THREADS) * 4;
                bReg[l] = *(const float4*)(B + (size_t)(k0 + BK) * N + flat);
            }
        }

#pragma unroll
        for (int kk = 0; kk < BK; kk += 8) {
            uint32_t ahi[MT][4], alo[MT][4];
#pragma unroll
            for (int mt = 0; mt < MT; mt++) {
                int r0 = wm0 + mt * 16 + p;
                f32_split(As[kk + q][r0],         ahi[mt][0], alo[mt][0]);
                f32_split(As[kk + q][r0 + 8],     ahi[mt][1], alo[mt][1]);
                f32_split(As[kk + q + 4][r0],     ahi[mt][2], alo[mt][2]);
                f32_split(As[kk + q + 4][r0 + 8], ahi[mt][3], alo[mt][3]);
            }
            uint32_t bhi[NT][2], blo[NT][2];
#pragma unroll
            for (int nt = 0; nt < NT; nt++) {
                int c0 = wn0 + nt * 8 + p;
                f32_split(Bs[kk + q][c0],     bhi[nt][0], blo[nt][0]);
                f32_split(Bs[kk + q + 4][c0], bhi[nt][1], blo[nt][1]);
            }
#pragma unroll
            for (int mt = 0; mt < MT; mt++)
#pragma unroll
                for (int nt = 0; nt < NT; nt++) {
                    mma_tf32(acc[mt][nt], ahi[mt], bhi[nt]);
                    mma_tf32(acc[mt][nt], ahi[mt], blo[nt]);
                    mma_tf32(acc[mt][nt], alo[mt], bhi[nt]);
                }
        }
        __syncthreads();
    }

#pragma unroll
    for (int mt = 0; mt < MT; mt++) {
        int row0 = m0 + wm0 + mt * 16 + p;
        int row1 = row0 + 8;
        float s0 = (row0 < M) ? scale[row0] : 0.0f;
        float s1 = (row1 < M) ? scale[row1] : 0.0f;
#pragma unroll
        for (int nt = 0; nt < NT; nt++) {
            int col = wn0 + nt * 8 + 2 * q;
            if (row0 < M) {
                float2 v = make_float2(acc[mt][nt][0] * s0, acc[mt][nt][1] * s0);
                *(float2*)(C + (size_t)row0 * N + col) = v;
            }
            if (row1 < M) {
                float2 v = make_float2(acc[mt][nt][2] * s1, acc[mt][nt][3] * s1);
                *(float2*)(C + (size_t)row1 * N + col) = v;
            }
        }
    }
}

// ---------------------------------------------------------------------------
// CSR pull aggregation: warp per node, register accumulate, one write.
// layer1: a1[node] = relu(dis[node] * (h1[node] + sum h1[src]) + b1)
// ---------------------------------------------------------------------------
__global__ __launch_bounds__(256) void k_agg1(const float* __restrict__ b1,
                                              int n) {
    int node = (blockIdx.x * blockDim.x + threadIdx.x) >> 5;
    int lane = threadIdx.x & 31;
    if (node >= n) return;
    int beg = g_off[node];
    int end = g_off[node + 1];

    float4 acc = ((const float4*)(g_h1 + (size_t)node * HID))[lane];  // self
    for (int j = beg; j < end; j += 32) {
        int myi = j + lane;
        int s = (myi < end) ? g_src[myi] : 0;
        int cnt = min(32, end - j);
        for (int k = 0; k < cnt; k++) {
            int sk = __shfl_sync(0xffffffff, s, k);
            float4 v = ((const float4*)(g_h1 + (size_t)sk * HID))[lane];
            acc.x += v.x; acc.y += v.y; acc.z += v.z; acc.w += v.w;
        }
    }
    float sc = g_dis[node];
    float4 b = ((const float4*)b1)[lane];
    float4 o;
    o.x = fmaxf(fmaf(acc.x, sc, b.x), 0.0f);
    o.y = fmaxf(fmaf(acc.y, sc, b.y), 0.0f);
    o.z = fmaxf(fmaf(acc.z, sc, b.z), 0.0f);
    o.w = fmaxf(fmaf(acc.w, sc, b.w), 0.0f);
    ((float4*)(g_a1 + (size_t)node * HID))[lane] = o;
}

// layer2: out[node] = dis[node] * (h2[node] + sum h2[src]) + b2
__global__ __launch_bounds__(256) void k_agg2(const float* __restrict__ b2,
                                              float* __restrict__ out, int n) {
    int node = (blockIdx.x * blockDim.x + threadIdx.x) >> 5;
    int lane = threadIdx.x & 31;
    if (node >= n) return;
    int beg = g_off[node];
    int end = g_off[node + 1];

    float2 acc = ((const float2*)(g_h2 + (size_t)node * OUTD))[lane];  // self
    for (int j = beg; j < end; j += 32) {
        int myi = j + lane;
        int s = (myi < end) ? g_src[myi] : 0;
        int cnt = min(32, end - j);
        for (int k = 0; k < cnt; k++) {
            int sk = __shfl_sync(0xffffffff, s, k);
            float2 v = ((const float2*)(g_h2 + (size_t)sk * OUTD))[lane];
            acc.x += v.x; acc.y += v.y;
        }
    }
    float sc = g_dis[node];
    float2 b = ((const float2*)b2)[lane];
    float2 o;
    o.x = fmaf(acc.x, sc, b.x);
    o.y = fmaf(acc.y, sc, b.y);
    ((float2*)(out + (size_t)node * OUTD))[lane] = o;
}

// ---------------------------------------------------------------------------
// launch
// ---------------------------------------------------------------------------
extern "C" void kernel_launch(void* const* d_in, const int* in_sizes, int n_in,
                              void* d_out, int out_size) {
    const float* x = nullptr;
    const void* ei = nullptr;
    const float* W1 = nullptr;
    const float* b1 = nullptr;
    const float* W2 = nullptr;
    const float* b2 = nullptr;
    for (int i = 0; i < n_in; i++) {
        switch (in_sizes[i]) {
            case NN * IND:   x  = (const float*)d_in[i]; break;
            case 2 * NE:     ei = d_in[i];               break;
            case IND * HID:  W1 = (const float*)d_in[i]; break;
            case HID:        b1 = (const float*)d_in[i]; break;
            case HID * OUTD: W2 = (const float*)d_in[i]; break;
            case OUTD:       b2 = (const float*)d_in[i]; break;
            default: break;
        }
    }
    float* out = (float*)d_out;
    const int n = NN;
    const int e = NE;

    float* h1;  cudaGetSymbolAddress((void**)&h1, g_h1);
    float* a1;  cudaGetSymbolAddress((void**)&a1, g_a1);
    float* h2;  cudaGetSymbolAddress((void**)&h2, g_h2);
    float* dis; cudaGetSymbolAddress((void**)&dis, g_dis);

    // edge normalization + CSR build
    k_detect<<<1, 32>>>((const int*)ei);
    k_convert<<<2048, 256>>>(ei, 2 * e);
    k_deg_zero<<<(n + 255) / 256, 256>>>(n);
    k_deg_count<<<1024, 256>>>(e);
    k_dis<<<(n + 255) / 256, 256>>>(n);
    k_scan1<<<NB, 1024>>>(n);
    k_scan2<<<1, 32>>>();
    k_scan3<<<(n + 255) / 256, 256>>>(n);
    k_scatter<<<1024, 256>>>(e);

    // layer 1
    tf32_gemm<IND, HID, 128, 32, 64, 32>
        <<<(n + 127) / 128, 256>>>(x, W1, h1, dis, n);
    {
        long long thr = (long long)n * 32;
        k_agg1<<<(int)((thr + 255) / 256), 256>>>(b1, n);
    }

    // layer 2
    tf32_gemm<HID, OUTD, 128, 32, 32, 32>
        <<<(n + 127) / 128, 256>>>(a1, W2, h2, dis, n);
    {
        long long thr = (long long)n * 32;
        k_agg2<<<(int)((thr + 255) / 256), 256>>>(b2, out, n);
    }
}